// round 12
// baseline (speedup 1.0000x reference)
#include <cuda_runtime.h>
#include <cstdint>

#define TPB      256
#define ROWS_PB  128

// ---- dynamic smem layout (persistent, B lives in registers) ----
#define SM_BIAS   0                        // 64 f32 = 256B
#define SM_A_HI   1024                     // 128 x 64 bf16, SW128 = 16KB  (B staged here once)
#define SM_A_LO   (1024 + 16384)           // 16KB
#define SM_T      (1024 + 32768)           // 33792: own region, 128*272 = 34816
#define T_STRIDE  272
#define SMEM_BYTES (33792 + 34816)         // 68608  (x2 CTAs = 137KB <= 228KB)

// SW128 swizzle on byte offset within a 128B-row tile
#define SW128(o) ((o) ^ (((o) >> 3) & 0x70))

// Precomputed W: bf16 hi (8KB) then lo (8KB), already SW128-swizzled.
__device__ __align__(16) unsigned char g_wpack[16384];

__device__ __forceinline__ uint32_t smem_u32(const void* p) {
    uint32_t a;
    asm("{ .reg .u64 t; cvta.to.shared.u64 t, %1; cvt.u32.u64 %0, t; }" : "=r"(a) : "l"(p));
    return a;
}

__device__ __forceinline__ uint32_t cvt_bf16x2(float a, float b) {
    uint32_t r;
    asm("cvt.rn.bf16x2.f32 %0, %1, %2;" : "=r"(r) : "f"(b), "f"(a));
    return r;
}

__device__ __forceinline__ void split4(float4 v, uint32_t& h0, uint32_t& h1,
                                       uint32_t& l0, uint32_t& l1) {
    h0 = cvt_bf16x2(v.x, v.y);
    h1 = cvt_bf16x2(v.z, v.w);
    float rx = v.x - __uint_as_float(h0 << 16);
    float ry = v.y - __uint_as_float(h0 & 0xFFFF0000u);
    float rz = v.z - __uint_as_float(h1 << 16);
    float rw = v.w - __uint_as_float(h1 & 0xFFFF0000u);
    l0 = cvt_bf16x2(rx, ry);
    l1 = cvt_bf16x2(rz, rw);
}

__device__ __forceinline__ void ldsm4(uint32_t* r, uint32_t addr) {
    asm volatile("ldmatrix.sync.aligned.m8n8.x4.shared.b16 {%0,%1,%2,%3}, [%4];"
                 : "=r"(r[0]), "=r"(r[1]), "=r"(r[2]), "=r"(r[3]) : "r"(addr));
}

__device__ __forceinline__ void mma_bf16(float* c, const uint32_t* a,
                                         uint32_t b0, uint32_t b1) {
    asm volatile(
        "mma.sync.aligned.m16n8k16.row.col.f32.bf16.bf16.f32 "
        "{%0,%1,%2,%3}, {%4,%5,%6,%7}, {%8,%9}, {%0,%1,%2,%3};"
        : "+f"(c[0]), "+f"(c[1]), "+f"(c[2]), "+f"(c[3])
        : "r"(a[0]), "r"(a[1]), "r"(a[2]), "r"(a[3]), "r"(b0), "r"(b1));
}

// ---- prologue: split + swizzle W into g_wpack ----
__global__ void prep_w(const float* __restrict__ w) {
    int i = blockIdx.x * blockDim.x + threadIdx.x;   // 0..1023 float4 chunks
    if (i < 1024) {
        float4 v = ((const float4*)w)[i];
        int o = i >> 4, c = i & 15;
        uint32_t h0, h1, l0, l1;
        split4(v, h0, h1, l0, l1);
        uint32_t off = SW128((uint32_t)(o * 128 + c * 8));
        *(uint2*)(g_wpack + off)        = make_uint2(h0, h1);
        *(uint2*)(g_wpack + 8192 + off) = make_uint2(l0, l1);
    }
}

__global__ void __launch_bounds__(TPB, 2)
fused_mma_scatter(const float* __restrict__ x,
                  const float* __restrict__ bias,
                  const int*   __restrict__ idx,
                  float*       __restrict__ out,
                  int n_rows, int n_tiles)
{
    extern __shared__ char smem[];
    const uint32_t sbase = smem_u32(smem);
    const int tid  = threadIdx.x;
    const int wid  = tid >> 5;
    const int lane = tid & 31;
    const int wg_row = wid & 3;     // 4 row-groups of 32 rows
    const int wg_col = wid >> 2;    // 2 col-groups of 32 cols

    // ---- one-time: stage packed W into A region, load B frags to regs ----
    {
        #pragma unroll
        for (int it = 0; it < 4; it++) {
            int i = it * TPB + tid;                 // 0..1023 16B chunks
            // hi 8KB -> SM_A_HI, lo 8KB -> SM_A_HI + 8192
            *(uint4*)(smem + SM_A_HI + i * 16) = *(const uint4*)(g_wpack + i * 16);
        }
        if (tid < 16) {
            float4 b4 = ((const float4*)bias)[tid];
            *(float4*)(smem + SM_BIAS + tid * 16) = b4;
        }
    }
    __syncthreads();

    // ldmatrix lane addressing (loop-invariant)
    const int rA  = (lane & 7) | (((lane >> 3) & 1) << 3);   // 0..15
    const int kbA = ((lane >> 4) & 1) * 16;
    const int rB  = (lane & 7) | (((lane >> 4) & 1) << 3);
    const int kbB = ((lane >> 3) & 1) * 16;
    const uint32_t swA = (uint32_t)((rA & 7) << 4);
    const uint32_t swB = (uint32_t)((rB & 7) << 4);

    // ---- B fragments: resident in registers for the whole kernel ----
    uint32_t BH[4][2][4], BL[4][2][4];      // [kt][jp][reg]
    {
        const uint32_t bBase = sbase + SM_A_HI +
                               (uint32_t)(wg_col * 4096 + rB * 128);
        #pragma unroll
        for (int kt = 0; kt < 4; kt++) {
            const uint32_t kOffB = (uint32_t)(kt * 32 + kbB) ^ swB;
            #pragma unroll
            for (int jp = 0; jp < 2; jp++) {
                ldsm4(BH[kt][jp], bBase + (uint32_t)(jp * 2048) + kOffB);
                ldsm4(BL[kt][jp], bBase + 8192u + (uint32_t)(jp * 2048) + kOffB);
            }
        }
    }
    // bias regs (loop-invariant)
    float bj[8];
    {
        const float* biasS = (const float*)(smem + SM_BIAS);
        const int cb = wg_col * 32 + (lane & 3) * 2;
        #pragma unroll
        for (int nt = 0; nt < 4; nt++) {
            float2 b2 = *(const float2*)(biasS + cb + nt * 8);
            bj[2 * nt]     = b2.x;
            bj[2 * nt + 1] = b2.y;
        }
    }
    __syncthreads();    // all warps own their B regs; A region now reusable

    for (int tile = blockIdx.x; tile < n_tiles; tile += gridDim.x) {
        const int row0 = tile * ROWS_PB;

        // prefetch scatter index
        int seg = 0;
        if (tid < ROWS_PB && row0 + tid < n_rows)
            seg = __ldg(idx + row0 + tid);

        // ---- stage A (T is a separate region: no drain needed here) ----
        {
            #pragma unroll
            for (int it = 0; it < 4; it++) {
                int i2 = it * 32 + lane;                    // 0..127 chunks
                int r  = wg_row * 32 + wg_col * 16 + (i2 >> 3);
                int c8 = i2 & 7;
                int grow = row0 + r;
                float v0 = 0.f, v1 = 0.f, v2 = 0.f, v3 = 0.f;
                float v4 = 0.f, v5 = 0.f, v6 = 0.f, v7 = 0.f;
                if (grow < n_rows) {
                    const float* p = x + (size_t)grow * 64 + c8 * 8;
                    asm volatile(
                        "ld.global.nc.L2::evict_first.v8.b32 "
                        "{%0,%1,%2,%3,%4,%5,%6,%7}, [%8];"
                        : "=f"(v0), "=f"(v1), "=f"(v2), "=f"(v3),
                          "=f"(v4), "=f"(v5), "=f"(v6), "=f"(v7)
                        : "l"(p));
                }
                uint32_t h0, h1, h2, h3, l0, l1, l2, l3;
                split4(make_float4(v0, v1, v2, v3), h0, h1, l0, l1);
                split4(make_float4(v4, v5, v6, v7), h2, h3, l2, l3);
                uint32_t off = SW128((uint32_t)(r * 128 + c8 * 16));
                *(uint4*)(smem + SM_A_HI + off) = make_uint4(h0, h1, h2, h3);
                *(uint4*)(smem + SM_A_LO + off) = make_uint4(l0, l1, l2, l3);
            }
        }
        // row-pair barrier: partner warp's 16 A-rows visible
        asm volatile("bar.sync %0, 64;" :: "r"(1 + wg_row) : "memory");

        // ---- MMA (A ldsm only; B from registers) ----
        uint32_t aBase[2];
        #pragma unroll
        for (int mt = 0; mt < 2; mt++)
            aBase[mt] = sbase + SM_A_HI +
                        (uint32_t)((wg_row * 32 + mt * 16 + rA) * 128);

        float acc[2][4][4];
        #pragma unroll
        for (int mt = 0; mt < 2; mt++)
            #pragma unroll
            for (int nt = 0; nt < 4; nt++)
                #pragma unroll
                for (int q = 0; q < 4; q++) acc[mt][nt][q] = 0.f;

        #pragma unroll
        for (int kt = 0; kt < 4; kt++) {
            const uint32_t kOffA = (uint32_t)(kt * 32 + kbA) ^ swA;
            uint32_t ah[2][4], al[2][4];
            #pragma unroll
            for (int mt = 0; mt < 2; mt++) {
                ldsm4(ah[mt], aBase[mt] + kOffA);
                ldsm4(al[mt], aBase[mt] + 16384u + kOffA);
            }
            #pragma unroll
            for (int jp = 0; jp < 2; jp++) {
                #pragma unroll
                for (int mt = 0; mt < 2; mt++) {
                    mma_bf16(acc[mt][2 * jp + 0], ah[mt], BH[kt][jp][0], BH[kt][jp][1]);
                    mma_bf16(acc[mt][2 * jp + 0], al[mt], BH[kt][jp][0], BH[kt][jp][1]);
                    mma_bf16(acc[mt][2 * jp + 0], ah[mt], BL[kt][jp][0], BL[kt][jp][1]);
                    mma_bf16(acc[mt][2 * jp + 1], ah[mt], BH[kt][jp][2], BH[kt][jp][3]);
                    mma_bf16(acc[mt][2 * jp + 1], al[mt], BH[kt][jp][2], BH[kt][jp][3]);
                    mma_bf16(acc[mt][2 * jp + 1], ah[mt], BL[kt][jp][2], BL[kt][jp][3]);
                }
            }
        }

        // ---- drain previous scatter (overlapped with staging+MMA above) ----
        asm volatile("cp.async.bulk.wait_group 0;" ::: "memory");
        __syncthreads();    // all bulk reads of T done + all MMAs done

        // ---- transpose accs (+bias) into linear rows for bulk-reduce ----
        {
            #pragma unroll
            for (int mt = 0; mt < 2; mt++)
                #pragma unroll
                for (int h = 0; h < 2; h++) {
                    int r = wg_row * 32 + mt * 16 + (lane >> 2) + 8 * h;
                    char* rowp = smem + SM_T + r * T_STRIDE +
                                 wg_col * 128 + (lane & 3) * 8;
                    #pragma unroll
                    for (int nt = 0; nt < 4; nt++) {
                        float2 v;
                        v.x = acc[mt][nt][2 * h]     + bj[2 * nt];
                        v.y = acc[mt][nt][2 * h + 1] + bj[2 * nt + 1];
                        *(float2*)(rowp + nt * 32) = v;
                    }
                }
        }
        asm volatile("fence.proxy.async.shared::cta;" ::: "memory");
        __syncthreads();

        // ---- scatter: one bulk reduce-add (256B) per row via TMA engine ----
        if (tid < ROWS_PB && row0 + tid < n_rows) {
            float* dst = out + (size_t)seg * 64;
            uint32_t src = sbase + SM_T + (uint32_t)(tid * T_STRIDE);
            asm volatile(
                "cp.reduce.async.bulk.global.shared::cta.bulk_group.add.f32 "
                "[%0], [%1], %2;"
                :: "l"(dst), "r"(src), "r"(256) : "memory");
        }
        asm volatile("cp.async.bulk.commit_group;" ::: "memory");
    }

    asm volatile("cp.async.bulk.wait_group 0;" ::: "memory");
}

extern "C" void kernel_launch(void* const* d_in, const int* in_sizes, int n_in,
                              void* d_out, int out_size) {
    const float* x    = (const float*)d_in[0];
    const float* w    = (const float*)d_in[1];
    const float* bias = (const float*)d_in[2];
    const int*   idx  = (const int*)d_in[3];
    float*       out  = (float*)d_out;

    const int n_rows  = in_sizes[0] / 64;
    const int n_tiles = (n_rows + ROWS_PB - 1) / ROWS_PB;

    cudaFuncSetAttribute(fused_mma_scatter,
                         cudaFuncAttributeMaxDynamicSharedMemorySize, SMEM_BYTES);

    cudaMemsetAsync(d_out, 0, (size_t)out_size * sizeof(float), 0);
    prep_w<<<4, 256>>>(w);

    int nsm = 148;
    cudaDeviceGetAttribute(&nsm, cudaDevAttrMultiProcessorCount, 0);
    int blocks = nsm * 2;
    if (blocks > n_tiles) blocks = n_tiles;

    fused_mma_scatter<<<blocks, TPB, SMEM_BYTES>>>(x, bias, idx, out,
                                                   n_rows, n_tiles);
}

// round 13
// speedup vs baseline: 1.2474x; 1.2474x over previous
#include <cuda_runtime.h>
#include <cstdint>

#define TPB      256
#define ROWS_PB  128

// ---- dynamic smem layout ----
#define SM_BIAS   0                        // 64 f32 = 256B
#define SM_A_HI   1024                     // 128 x 64 bf16, SW128 = 16KB
#define SM_A_LO   (1024 + 16384)           // 16KB
#define SM_B_HI   (1024 + 32768)           // 64 x 64 bf16, SW128 = 8KB
#define SM_B_LO   (1024 + 32768 + 8192)    // 8KB
#define SM_T      1024                     // transpose region (reuses A/B, post-sync)
#define T_STRIDE  272                      // 256B row + 16B pad
#define SMEM_BYTES (1024 + 32768 + 16384)  // 50176

// SW128 swizzle on byte offset within a 128B-row tile
#define SW128(o) ((o) ^ (((o) >> 3) & 0x70))

// Precomputed W: bf16 hi (8KB) then lo (8KB), already SW128-swizzled.
__device__ __align__(16) unsigned char g_wpack[16384];

__device__ __forceinline__ uint32_t smem_u32(const void* p) {
    uint32_t a;
    asm("{ .reg .u64 t; cvta.to.shared.u64 t, %1; cvt.u32.u64 %0, t; }" : "=r"(a) : "l"(p));
    return a;
}

__device__ __forceinline__ uint32_t cvt_bf16x2(float a, float b) {
    uint32_t r;
    asm("cvt.rn.bf16x2.f32 %0, %1, %2;" : "=r"(r) : "f"(b), "f"(a));
    return r;
}

__device__ __forceinline__ void split4(float4 v, uint32_t& h0, uint32_t& h1,
                                       uint32_t& l0, uint32_t& l1) {
    h0 = cvt_bf16x2(v.x, v.y);
    h1 = cvt_bf16x2(v.z, v.w);
    float rx = v.x - __uint_as_float(h0 << 16);
    float ry = v.y - __uint_as_float(h0 & 0xFFFF0000u);
    float rz = v.z - __uint_as_float(h1 << 16);
    float rw = v.w - __uint_as_float(h1 & 0xFFFF0000u);
    l0 = cvt_bf16x2(rx, ry);
    l1 = cvt_bf16x2(rz, rw);
}

__device__ __forceinline__ void ldsm4(uint32_t* r, uint32_t addr) {
    asm volatile("ldmatrix.sync.aligned.m8n8.x4.shared.b16 {%0,%1,%2,%3}, [%4];"
                 : "=r"(r[0]), "=r"(r[1]), "=r"(r[2]), "=r"(r[3]) : "r"(addr));
}

__device__ __forceinline__ void mma_bf16(float* c, const uint32_t* a,
                                         uint32_t b0, uint32_t b1) {
    asm volatile(
        "mma.sync.aligned.m16n8k16.row.col.f32.bf16.bf16.f32 "
        "{%0,%1,%2,%3}, {%4,%5,%6,%7}, {%8,%9}, {%0,%1,%2,%3};"
        : "+f"(c[0]), "+f"(c[1]), "+f"(c[2]), "+f"(c[3])
        : "r"(a[0]), "r"(a[1]), "r"(a[2]), "r"(a[3]), "r"(b0), "r"(b1));
}

// ---- prologue: split + swizzle W into g_wpack ----
__global__ void prep_w(const float* __restrict__ w) {
    int i = blockIdx.x * blockDim.x + threadIdx.x;   // 0..1023 float4 chunks
    if (i < 1024) {
        float4 v = ((const float4*)w)[i];
        int o = i >> 4, c = i & 15;
        uint32_t h0, h1, l0, l1;
        split4(v, h0, h1, l0, l1);
        uint32_t off = SW128((uint32_t)(o * 128 + c * 8));
        *(uint2*)(g_wpack + off)        = make_uint2(h0, h1);
        *(uint2*)(g_wpack + 8192 + off) = make_uint2(l0, l1);
    }
}

__global__ void __launch_bounds__(TPB, 4)
fused_mma_scatter(const float* __restrict__ x,
                  const float* __restrict__ bias,
                  const int*   __restrict__ idx,
                  float*       __restrict__ out,
                  int n_rows)
{
    extern __shared__ char smem[];
    const uint32_t sbase = smem_u32(smem);
    const int tid  = threadIdx.x;
    const int wid  = tid >> 5;
    const int lane = tid & 31;
    const int wg_row = wid & 3;     // 4 row-groups of 32 rows
    const int wg_col = wid >> 2;    // 2 col-groups of 32 cols
    const int row0 = blockIdx.x * ROWS_PB;

    // ---- prefetch scatter index early (hides idx LDG latency) ----
    int seg = 0;
    if (tid < ROWS_PB && row0 + tid < n_rows)
        seg = __ldg(idx + row0 + tid);

    // ---- W: each col-group (4 warps) copies ITS 8KB half via cp.async ----
    {
        const int gtid = wg_row * 32 + lane;            // 0..127 within col-group
        const uint32_t half = (uint32_t)(wg_col * 4096);
        #pragma unroll
        for (int it = 0; it < 2; it++) {
            uint32_t c = (uint32_t)(it * 128 + gtid) * 16;   // 0..4080
            asm volatile("cp.async.cg.shared.global [%0], [%1], 16;"
                         :: "r"(sbase + SM_B_HI + half + c),
                            "l"(g_wpack + half + c) : "memory");
            asm volatile("cp.async.cg.shared.global [%0], [%1], 16;"
                         :: "r"(sbase + SM_B_LO + half + c),
                            "l"(g_wpack + 8192 + half + c) : "memory");
        }
        asm volatile("cp.async.commit_group;" ::: "memory");
    }
    if (tid < 16) {
        float4 b4 = ((const float4*)bias)[tid];
        *(float4*)(smem + SM_BIAS + tid * 16) = b4;
    }

    // ---- stage A: row-pair {wg_row} covers rows [wg_row*32, +32) ----
    {
        #pragma unroll
        for (int it = 0; it < 4; it++) {
            int i2 = it * 32 + lane;                    // 0..127 chunks
            int r  = wg_row * 32 + wg_col * 16 + (i2 >> 3);
            int c8 = i2 & 7;
            int grow = row0 + r;
            float v0 = 0.f, v1 = 0.f, v2 = 0.f, v3 = 0.f;
            float v4 = 0.f, v5 = 0.f, v6 = 0.f, v7 = 0.f;
            if (grow < n_rows) {
                const float* p = x + (size_t)grow * 64 + c8 * 8;
                asm volatile(
                    "ld.global.nc.L2::evict_first.v8.b32 "
                    "{%0,%1,%2,%3,%4,%5,%6,%7}, [%8];"
                    : "=f"(v0), "=f"(v1), "=f"(v2), "=f"(v3),
                      "=f"(v4), "=f"(v5), "=f"(v6), "=f"(v7)
                    : "l"(p));
            }
            uint32_t h0, h1, h2, h3, l0, l1, l2, l3;
            split4(make_float4(v0, v1, v2, v3), h0, h1, l0, l1);
            split4(make_float4(v4, v5, v6, v7), h2, h3, l2, l3);
            uint32_t off = SW128((uint32_t)(r * 128 + c8 * 16));
            *(uint4*)(smem + SM_A_HI + off) = make_uint4(h0, h1, h2, h3);
            *(uint4*)(smem + SM_A_LO + off) = make_uint4(l0, l1, l2, l3);
        }
    }
    // row-pair barrier: partner warp's 16 A-rows visible
    asm volatile("bar.sync %0, 64;" :: "r"(1 + wg_row) : "memory");
    // B visibility: own copies done, then col-group barrier
    asm volatile("cp.async.wait_group 0;" ::: "memory");
    asm volatile("bar.sync %0, 128;" :: "r"(5 + wg_col) : "memory");

    // ---- ldmatrix lane addressing ----
    const int rA  = (lane & 7) | (((lane >> 3) & 1) << 3);   // 0..15
    const int kbA = ((lane >> 4) & 1) * 16;
    const int rB  = (lane & 7) | (((lane >> 4) & 1) << 3);
    const int kbB = ((lane >> 3) & 1) * 16;

    const uint32_t swA = (uint32_t)((rA & 7) << 4);
    const uint32_t swB = (uint32_t)((rB & 7) << 4);

    uint32_t aBase[2];
    #pragma unroll
    for (int mt = 0; mt < 2; mt++)
        aBase[mt] = sbase + SM_A_HI +
                    (uint32_t)((wg_row * 32 + mt * 16 + rA) * 128);
    const uint32_t bBase = sbase + SM_B_HI +
                           (uint32_t)(wg_col * 4096 + rB * 128);

    float acc[2][4][4];
    #pragma unroll
    for (int mt = 0; mt < 2; mt++)
        #pragma unroll
        for (int nt = 0; nt < 4; nt++)
            #pragma unroll
            for (int q = 0; q < 4; q++) acc[mt][nt][q] = 0.f;

    #pragma unroll
    for (int kt = 0; kt < 4; kt++) {
        const uint32_t kOffA = (uint32_t)(kt * 32 + kbA) ^ swA;
        const uint32_t kOffB = (uint32_t)(kt * 32 + kbB) ^ swB;

        uint32_t ah[2][4], al[2][4];
        #pragma unroll
        for (int mt = 0; mt < 2; mt++) {
            ldsm4(ah[mt], aBase[mt] + kOffA);
            ldsm4(al[mt], aBase[mt] + 16384u + kOffA);
        }

        #pragma unroll
        for (int jp = 0; jp < 2; jp++) {
            uint32_t bh[4], bl[4];
            uint32_t baddr = bBase + (uint32_t)(jp * 2048) + kOffB;
            ldsm4(bh, baddr);
            ldsm4(bl, baddr + 8192u);

            #pragma unroll
            for (int mt = 0; mt < 2; mt++) {
                mma_bf16(acc[mt][2 * jp + 0], ah[mt], bh[0], bh[1]);
                mma_bf16(acc[mt][2 * jp + 0], al[mt], bh[0], bh[1]);
                mma_bf16(acc[mt][2 * jp + 0], ah[mt], bl[0], bl[1]);
                mma_bf16(acc[mt][2 * jp + 1], ah[mt], bh[2], bh[3]);
                mma_bf16(acc[mt][2 * jp + 1], al[mt], bh[2], bh[3]);
                mma_bf16(acc[mt][2 * jp + 1], ah[mt], bl[2], bl[3]);
            }
        }
    }
    __syncthreads();    // everyone done with A/B smem (region reused below)

    // ---- bias regs for this lane's columns ----
    float bj[8];
    {
        const float* biasS = (const float*)(smem + SM_BIAS);
        const int cb = wg_col * 32 + (lane & 3) * 2;
        #pragma unroll
        for (int nt = 0; nt < 4; nt++) {
            float2 b2 = *(const float2*)(biasS + cb + nt * 8);
            bj[2 * nt]     = b2.x;
            bj[2 * nt + 1] = b2.y;
        }
    }

    // ---- transpose accs (+bias) into linear rows for bulk-reduce ----
    {
        #pragma unroll
        for (int mt = 0; mt < 2; mt++)
            #pragma unroll
            for (int h = 0; h < 2; h++) {
                int r = wg_row * 32 + mt * 16 + (lane >> 2) + 8 * h;
                char* rowp = smem + SM_T + r * T_STRIDE +
                             wg_col * 128 + (lane & 3) * 8;
                #pragma unroll
                for (int nt = 0; nt < 4; nt++) {
                    float2 v;
                    v.x = acc[mt][nt][2 * h]     + bj[2 * nt];
                    v.y = acc[mt][nt][2 * h + 1] + bj[2 * nt + 1];
                    *(float2*)(rowp + nt * 32) = v;
                }
            }
    }
    asm volatile("fence.proxy.async.shared::cta;" ::: "memory");
    __syncthreads();

    // ---- scatter: one bulk reduce-add (256B) per row via TMA engine ----
    {
        if (tid < ROWS_PB && row0 + tid < n_rows) {
            float* dst = out + (size_t)seg * 64;
            uint32_t src = sbase + SM_T + (uint32_t)(tid * T_STRIDE);
            asm volatile(
                "cp.reduce.async.bulk.global.shared::cta.bulk_group.add.f32 "
                "[%0], [%1], %2;"
                :: "l"(dst), "r"(src), "r"(256) : "memory");
        }
        asm volatile("cp.async.bulk.commit_group;" ::: "memory");
        asm volatile("cp.async.bulk.wait_group 0;" ::: "memory");
    }
}

extern "C" void kernel_launch(void* const* d_in, const int* in_sizes, int n_in,
                              void* d_out, int out_size) {
    const float* x    = (const float*)d_in[0];
    const float* w    = (const float*)d_in[1];
    const float* bias = (const float*)d_in[2];
    const int*   idx  = (const int*)d_in[3];
    float*       out  = (float*)d_out;

    const int n_rows = in_sizes[0] / 64;

    cudaFuncSetAttribute(fused_mma_scatter,
                         cudaFuncAttributeMaxDynamicSharedMemorySize, SMEM_BYTES);

    // ---- fork: memset(out) on a side stream, prep_w on the main stream ----
    // (independent work; join before the main kernel). Standard capture-legal
    // event fork/join — no device allocations involved.
    cudaStream_t s2;
    cudaStreamCreateWithFlags(&s2, cudaStreamNonBlocking);
    cudaEvent_t eFork, eJoin;
    cudaEventCreateWithFlags(&eFork, cudaEventDisableTiming);
    cudaEventCreateWithFlags(&eJoin, cudaEventDisableTiming);

    cudaEventRecord(eFork, 0);
    cudaStreamWaitEvent(s2, eFork, 0);
    cudaMemsetAsync(d_out, 0, (size_t)out_size * sizeof(float), s2);
    cudaEventRecord(eJoin, s2);

    prep_w<<<4, 256>>>(w);                 // runs concurrently with memset
    cudaStreamWaitEvent(0, eJoin, 0);      // join: memset done before scatters

    int blocks = (n_rows + ROWS_PB - 1) / ROWS_PB;
    fused_mma_scatter<<<blocks, TPB, SMEM_BYTES>>>(x, bias, idx, out, n_rows);
}

// round 14
// speedup vs baseline: 1.5316x; 1.2279x over previous
#include <cuda_runtime.h>
#include <cstdint>

#define TPB      256
#define ROWS_PB  128

// ---- dynamic smem layout (fp16 single-plane) ----
#define SM_BIAS   0                        // 64 f32 = 256B
#define SM_A      1024                     // 128 x 64 fp16, SW128 = 16KB
#define SM_B      (1024 + 16384)           // 64 x 64 fp16, SW128 = 8KB
#define SM_T      1024                     // transpose region (reuses A/B, post-sync)
#define T_STRIDE  272                      // 256B row + 16B pad
#define SMEM_BYTES (1024 + 34816)          // 35840 (T: 128*272)

// SW128 swizzle on byte offset within a 128B-row tile
#define SW128(o) ((o) ^ (((o) >> 3) & 0x70))

// Precomputed W: fp16, SW128-swizzled, 8KB.
__device__ __align__(16) unsigned char g_wpack[8192];

__device__ __forceinline__ uint32_t smem_u32(const void* p) {
    uint32_t a;
    asm("{ .reg .u64 t; cvta.to.shared.u64 t, %1; cvt.u32.u64 %0, t; }" : "=r"(a) : "l"(p));
    return a;
}

// pack two f32 -> f16x2 (memory order [a, b]), round-to-nearest
__device__ __forceinline__ uint32_t cvt_f16x2(float a, float b) {
    uint32_t r;
    asm("cvt.rn.f16x2.f32 %0, %1, %2;" : "=r"(r) : "f"(b), "f"(a));
    return r;
}

__device__ __forceinline__ void ldsm4(uint32_t* r, uint32_t addr) {
    asm volatile("ldmatrix.sync.aligned.m8n8.x4.shared.b16 {%0,%1,%2,%3}, [%4];"
                 : "=r"(r[0]), "=r"(r[1]), "=r"(r[2]), "=r"(r[3]) : "r"(addr));
}

__device__ __forceinline__ void mma_f16(float* c, const uint32_t* a,
                                        uint32_t b0, uint32_t b1) {
    asm volatile(
        "mma.sync.aligned.m16n8k16.row.col.f32.f16.f16.f32 "
        "{%0,%1,%2,%3}, {%4,%5,%6,%7}, {%8,%9}, {%0,%1,%2,%3};"
        : "+f"(c[0]), "+f"(c[1]), "+f"(c[2]), "+f"(c[3])
        : "r"(a[0]), "r"(a[1]), "r"(a[2]), "r"(a[3]), "r"(b0), "r"(b1));
}

// ---- prologue: convert + swizzle W (fp16) into g_wpack ----
__global__ void prep_w(const float* __restrict__ w) {
    int i = blockIdx.x * blockDim.x + threadIdx.x;   // 0..1023 float4 chunks
    if (i < 1024) {
        float4 v = ((const float4*)w)[i];
        int o = i >> 4, c = i & 15;
        uint32_t h0 = cvt_f16x2(v.x, v.y);
        uint32_t h1 = cvt_f16x2(v.z, v.w);
        uint32_t off = SW128((uint32_t)(o * 128 + c * 8));
        *(uint2*)(g_wpack + off) = make_uint2(h0, h1);
    }
}

__global__ void __launch_bounds__(TPB, 4)
fused_mma_scatter(const float* __restrict__ x,
                  const float* __restrict__ bias,
                  const int*   __restrict__ idx,
                  float*       __restrict__ out,
                  int n_rows)
{
    extern __shared__ char smem[];
    const uint32_t sbase = smem_u32(smem);
    const int tid  = threadIdx.x;
    const int wid  = tid >> 5;
    const int lane = tid & 31;
    const int wg_row = wid & 3;     // 4 row-groups of 32 rows
    const int wg_col = wid >> 2;    // 2 col-groups of 32 cols
    const int row0 = blockIdx.x * ROWS_PB;

    // ---- prefetch scatter index early ----
    int seg = 0;
    if (tid < ROWS_PB && row0 + tid < n_rows)
        seg = __ldg(idx + row0 + tid);

    // ---- W: each col-group (4 warps) copies ITS 4KB half via cp.async ----
    {
        const int gtid = wg_row * 32 + lane;            // 0..127 within col-group
        const uint32_t half = (uint32_t)(wg_col * 4096);
        #pragma unroll
        for (int it = 0; it < 2; it++) {
            uint32_t c = (uint32_t)(it * 128 + gtid) * 16;   // 0..4080
            asm volatile("cp.async.cg.shared.global [%0], [%1], 16;"
                         :: "r"(sbase + SM_B + half + c),
                            "l"(g_wpack + half + c) : "memory");
        }
        asm volatile("cp.async.commit_group;" ::: "memory");
    }
    if (tid < 16) {
        float4 b4 = ((const float4*)bias)[tid];
        *(float4*)(smem + SM_BIAS + tid * 16) = b4;
    }

    // ---- stage A (fp16): row-pair {wg_row}, this warp stages 16 rows ----
    {
        #pragma unroll
        for (int it = 0; it < 4; it++) {
            int i2 = it * 32 + lane;                    // 0..127 32B chunks
            int r  = wg_row * 32 + wg_col * 16 + (i2 >> 3);
            int c8 = i2 & 7;
            int grow = row0 + r;
            float v0 = 0.f, v1 = 0.f, v2 = 0.f, v3 = 0.f;
            float v4 = 0.f, v5 = 0.f, v6 = 0.f, v7 = 0.f;
            if (grow < n_rows) {
                const float* p = x + (size_t)grow * 64 + c8 * 8;
                asm volatile(
                    "ld.global.nc.L2::evict_first.v8.b32 "
                    "{%0,%1,%2,%3,%4,%5,%6,%7}, [%8];"
                    : "=f"(v0), "=f"(v1), "=f"(v2), "=f"(v3),
                      "=f"(v4), "=f"(v5), "=f"(v6), "=f"(v7)
                    : "l"(p));
            }
            uint32_t p0 = cvt_f16x2(v0, v1);
            uint32_t p1 = cvt_f16x2(v2, v3);
            uint32_t p2 = cvt_f16x2(v4, v5);
            uint32_t p3 = cvt_f16x2(v6, v7);
            uint32_t off = SW128((uint32_t)(r * 128 + c8 * 16));
            *(uint4*)(smem + SM_A + off) = make_uint4(p0, p1, p2, p3);
        }
    }
    // row-pair barrier: partner warp's 16 A-rows visible
    asm volatile("bar.sync %0, 64;" :: "r"(1 + wg_row) : "memory");
    // B visibility: own copies done, then col-group barrier
    asm volatile("cp.async.wait_group 0;" ::: "memory");
    asm volatile("bar.sync %0, 128;" :: "r"(5 + wg_col) : "memory");

    // ---- ldmatrix lane addressing ----
    const int rA  = (lane & 7) | (((lane >> 3) & 1) << 3);   // 0..15
    const int kbA = ((lane >> 4) & 1) * 16;
    const int rB  = (lane & 7) | (((lane >> 4) & 1) << 3);
    const int kbB = ((lane >> 3) & 1) * 16;

    const uint32_t swA = (uint32_t)((rA & 7) << 4);
    const uint32_t swB = (uint32_t)((rB & 7) << 4);

    uint32_t aBase[2];
    #pragma unroll
    for (int mt = 0; mt < 2; mt++)
        aBase[mt] = sbase + SM_A +
                    (uint32_t)((wg_row * 32 + mt * 16 + rA) * 128);
    const uint32_t bBase = sbase + SM_B +
                           (uint32_t)(wg_col * 4096 + rB * 128);

    float acc[2][4][4];
    #pragma unroll
    for (int mt = 0; mt < 2; mt++)
        #pragma unroll
        for (int nt = 0; nt < 4; nt++)
            #pragma unroll
            for (int q = 0; q < 4; q++) acc[mt][nt][q] = 0.f;

    #pragma unroll
    for (int kt = 0; kt < 4; kt++) {
        const uint32_t kOffA = (uint32_t)(kt * 32 + kbA) ^ swA;
        const uint32_t kOffB = (uint32_t)(kt * 32 + kbB) ^ swB;

        uint32_t ah[2][4];
        #pragma unroll
        for (int mt = 0; mt < 2; mt++)
            ldsm4(ah[mt], aBase[mt] + kOffA);

        #pragma unroll
        for (int jp = 0; jp < 2; jp++) {
            uint32_t bh[4];
            ldsm4(bh, bBase + (uint32_t)(jp * 2048) + kOffB);

            #pragma unroll
            for (int mt = 0; mt < 2; mt++) {
                mma_f16(acc[mt][2 * jp + 0], ah[mt], bh[0], bh[1]);
                mma_f16(acc[mt][2 * jp + 1], ah[mt], bh[2], bh[3]);
            }
        }
    }
    __syncthreads();    // everyone done with A/B smem (T reuses them)

    // ---- bias regs for this lane's columns ----
    float bj[8];
    {
        const float* biasS = (const float*)(smem + SM_BIAS);
        const int cb = wg_col * 32 + (lane & 3) * 2;
        #pragma unroll
        for (int nt = 0; nt < 4; nt++) {
            float2 b2 = *(const float2*)(biasS + cb + nt * 8);
            bj[2 * nt]     = b2.x;
            bj[2 * nt + 1] = b2.y;
        }
    }

    // ---- transpose accs (+bias) into linear rows for bulk-reduce ----
    {
        #pragma unroll
        for (int mt = 0; mt < 2; mt++)
            #pragma unroll
            for (int h = 0; h < 2; h++) {
                int r = wg_row * 32 + mt * 16 + (lane >> 2) + 8 * h;
                char* rowp = smem + SM_T + r * T_STRIDE +
                             wg_col * 128 + (lane & 3) * 8;
                #pragma unroll
                for (int nt = 0; nt < 4; nt++) {
                    float2 v;
                    v.x = acc[mt][nt][2 * h]     + bj[2 * nt];
                    v.y = acc[mt][nt][2 * h + 1] + bj[2 * nt + 1];
                    *(float2*)(rowp + nt * 32) = v;
                }
            }
    }
    asm volatile("fence.proxy.async.shared::cta;" ::: "memory");
    __syncthreads();

    // ---- scatter: one bulk reduce-add (256B) per row via TMA engine ----
    {
        if (tid < ROWS_PB && row0 + tid < n_rows) {
            float* dst = out + (size_t)seg * 64;
            uint32_t src = sbase + SM_T + (uint32_t)(tid * T_STRIDE);
            asm volatile(
                "cp.reduce.async.bulk.global.shared::cta.bulk_group.add.f32 "
                "[%0], [%1], %2;"
                :: "l"(dst), "r"(src), "r"(256) : "memory");
        }
        asm volatile("cp.async.bulk.commit_group;" ::: "memory");
        asm volatile("cp.async.bulk.wait_group 0;" ::: "memory");
    }
}

extern "C" void kernel_launch(void* const* d_in, const int* in_sizes, int n_in,
                              void* d_out, int out_size) {
    const float* x    = (const float*)d_in[0];
    const float* w    = (const float*)d_in[1];
    const float* bias = (const float*)d_in[2];
    const int*   idx  = (const int*)d_in[3];
    float*       out  = (float*)d_out;

    const int n_rows = in_sizes[0] / 64;

    cudaFuncSetAttribute(fused_mma_scatter,
                         cudaFuncAttributeMaxDynamicSharedMemorySize, SMEM_BYTES);

    cudaMemsetAsync(d_out, 0, (size_t)out_size * sizeof(float), 0);
    prep_w<<<4, 256>>>(w);

    int blocks = (n_rows + ROWS_PB - 1) / ROWS_PB;
    fused_mma_scatter<<<blocks, TPB, SMEM_BYTES>>>(x, bias, idx, out, n_rows);
}